// round 1
// baseline (speedup 1.0000x reference)
#include <cuda_runtime.h>

// out = cumprod_j( cos(w_j) * cos(x @ W_pre^T + b_pre) ) @ W_post^T + b_post
//
// Analytic reduction of the quantum layer:
//   z_j       = cos(q_weights_j) * cos(angle_j)      (single-qubit <Z>)
//   <Z_i>     = prod_{j<=i} z_j                      (CNOT chain = prefix-XOR)
//
// One block per batch row. 256 threads.
//   Phase 1: 8 warps x 2 qubits/warp -> 16 dot products of length 1024.
//   Phase 2: thread 0: 16-element cos + cumprod -> smem zq[16].
//   Phase 3: 1024 outputs, 4 per thread, 16-length dot vs zq.

#define NQ   16
#define DIN  1024
#define DOUT 1024

__global__ __launch_bounds__(256, 8)
void quantum_projector_kernel(const float* __restrict__ x,
                              const float* __restrict__ W_pre,
                              const float* __restrict__ b_pre,
                              const float* __restrict__ q_weights,
                              const float* __restrict__ W_post,
                              const float* __restrict__ b_post,
                              float* __restrict__ out)
{
    __shared__ float s_angle[NQ];
    __shared__ float s_zq[NQ];

    const int row  = blockIdx.x;
    const int tid  = threadIdx.x;
    const int warp = tid >> 5;
    const int lane = tid & 31;
    const int half = lane >> 4;      // 0 or 1: which qubit within the warp
    const int sub  = lane & 15;      // lane within the 16-lane reduction group
    const int q    = warp * 2 + half;

    // ---- Phase 1: angles[q] = dot(x[row,:], W_pre[q,:]) + b_pre[q] ----
    const float4* __restrict__ x4 = reinterpret_cast<const float4*>(x + row * DIN);
    const float4* __restrict__ w4 = reinterpret_cast<const float4*>(W_pre + q * DIN);

    float acc = 0.f;
#pragma unroll
    for (int i = 0; i < 16; i++) {
        const int k = sub + 16 * i;       // 256 float4 per row, 16 per lane
        float4 xv = x4[k];
        float4 wv = w4[k];
        acc += xv.x * wv.x + xv.y * wv.y + xv.z * wv.z + xv.w * wv.w;
    }
    // reduce across the 16-lane group (xor offsets < 16 stay inside the group)
#pragma unroll
    for (int off = 8; off >= 1; off >>= 1)
        acc += __shfl_xor_sync(0xffffffffu, acc, off);

    if (sub == 0)
        s_angle[q] = acc + b_pre[q];
    __syncthreads();

    // ---- Phase 2: zq = cumprod(cos(w) * cos(angle)) ----
    if (tid == 0) {
        float p = 1.f;
#pragma unroll
        for (int j = 0; j < NQ; j++) {
            p *= cosf(q_weights[j]) * cosf(s_angle[j]);
            s_zq[j] = p;
        }
    }
    __syncthreads();

    // ---- Phase 3: out[row, o] = b_post[o] + dot(zq, W_post[o, :]) ----
    float zq[NQ];
#pragma unroll
    for (int j = 0; j < NQ; j++) zq[j] = s_zq[j];

    const float4* __restrict__ Wp4 = reinterpret_cast<const float4*>(W_post);
    float* __restrict__ out_row = out + row * DOUT;

#pragma unroll
    for (int r = 0; r < 4; r++) {
        const int o = tid + 256 * r;
        float4 w0 = Wp4[o * 4 + 0];
        float4 w1 = Wp4[o * 4 + 1];
        float4 w2 = Wp4[o * 4 + 2];
        float4 w3 = Wp4[o * 4 + 3];
        float d =  zq[0]  * w0.x + zq[1]  * w0.y + zq[2]  * w0.z + zq[3]  * w0.w
                 + zq[4]  * w1.x + zq[5]  * w1.y + zq[6]  * w1.z + zq[7]  * w1.w
                 + zq[8]  * w2.x + zq[9]  * w2.y + zq[10] * w2.z + zq[11] * w2.w
                 + zq[12] * w3.x + zq[13] * w3.y + zq[14] * w3.z + zq[15] * w3.w;
        out_row[o] = b_post[o] + d;
    }
}

extern "C" void kernel_launch(void* const* d_in, const int* in_sizes, int n_in,
                              void* d_out, int out_size)
{
    const float* x         = (const float*)d_in[0];   // [256, 1024]
    const float* W_pre     = (const float*)d_in[1];   // [16, 1024]
    const float* b_pre     = (const float*)d_in[2];   // [16]
    const float* q_weights = (const float*)d_in[3];   // [16]
    const float* W_post    = (const float*)d_in[4];   // [1024, 16]
    const float* b_post    = (const float*)d_in[5];   // [1024]
    float* out             = (float*)d_out;           // [256, 1024]

    quantum_projector_kernel<<<256, 256>>>(x, W_pre, b_pre, q_weights,
                                           W_post, b_post, out);
}

// round 2
// speedup vs baseline: 1.2179x; 1.2179x over previous
#include <cuda_runtime.h>

// out = cumprod_j( cos(w_j) * cos(x @ W_pre^T + b_pre) ) @ W_post^T + b_post
//
// Analytic reduction of the quantum layer:
//   z_j   = cos(q_weights_j) * cos(angle_j)   (single-qubit <Z>)
//   <Z_i> = prod_{j<=i} z_j                   (CNOT chain = prefix-XOR)
//
// One block per batch row, 512 threads (16 warps).
//   Phase 1: warp j computes angle_j = dot(x[row], W_pre[j]) (8 float4/lane, warp-reduce)
//   Prefetch: each thread loads its 2 W_post rows (8 contiguous float4) + b_post
//   Phase 2: warp 0, 16 lanes: cos + shfl_up inclusive prefix-product
//   Phase 3: each thread: 2 outputs = 16-dot(zq, W_post rows) from registers, float2 store

#define NQ   16
#define DIN  1024
#define DOUT 1024

__global__ __launch_bounds__(512, 2)
void quantum_projector_kernel(const float* __restrict__ x,
                              const float* __restrict__ W_pre,
                              const float* __restrict__ b_pre,
                              const float* __restrict__ q_weights,
                              const float* __restrict__ W_post,
                              const float* __restrict__ b_post,
                              float* __restrict__ out)
{
    __shared__ float s_angle[NQ];
    __shared__ float s_zq[NQ];

    const int row  = blockIdx.x;
    const int tid  = threadIdx.x;
    const int warp = tid >> 5;       // 16 warps = 16 qubits
    const int lane = tid & 31;

    // ---- Phase 1: angle[warp] = dot(x[row,:], W_pre[warp,:]) + b_pre[warp] ----
    {
        const float4* __restrict__ x4 = reinterpret_cast<const float4*>(x + row * DIN);
        const float4* __restrict__ w4 = reinterpret_cast<const float4*>(W_pre + warp * DIN);

        float acc = 0.f;
#pragma unroll
        for (int i = 0; i < 8; i++) {
            const int k = lane + 32 * i;         // 256 float4 per row, 8 per lane
            float4 xv = x4[k];
            float4 wv = w4[k];
            acc += xv.x * wv.x + xv.y * wv.y + xv.z * wv.z + xv.w * wv.w;
        }
#pragma unroll
        for (int off = 16; off >= 1; off >>= 1)
            acc += __shfl_xor_sync(0xffffffffu, acc, off);

        if (lane == 0)
            s_angle[warp] = acc + b_pre[warp];
    }

    // ---- Prefetch phase-3 operands (independent; latency hidden under scan) ----
    // Thread t covers outputs o0=2t, o1=2t+1: W_post[o0..o1, 0..15] = float4[8t .. 8t+7]
    const float4* __restrict__ Wp4 = reinterpret_cast<const float4*>(W_post);
    float4 wreg[8];
#pragma unroll
    for (int i = 0; i < 8; i++)
        wreg[i] = Wp4[8 * tid + i];
    const float2 bp = reinterpret_cast<const float2*>(b_post)[tid];

    __syncthreads();

    // ---- Phase 2: zq = inclusive prefix product of cos(w_j)*cos(angle_j) ----
    if (warp == 0) {
        float v = 1.f;
        if (lane < NQ)
            v = cosf(q_weights[lane]) * cosf(s_angle[lane]);
#pragma unroll
        for (int off = 1; off <= 8; off <<= 1) {
            float t = __shfl_up_sync(0xffffffffu, v, off);
            if (lane >= off) v *= t;
        }
        if (lane < NQ)
            s_zq[lane] = v;
    }
    __syncthreads();

    // ---- Phase 3: two outputs per thread from registers ----
    float zq[NQ];
#pragma unroll
    for (int j = 0; j < NQ; j++) zq[j] = s_zq[j];

    float d0 = zq[0]  * wreg[0].x + zq[1]  * wreg[0].y + zq[2]  * wreg[0].z + zq[3]  * wreg[0].w
             + zq[4]  * wreg[1].x + zq[5]  * wreg[1].y + zq[6]  * wreg[1].z + zq[7]  * wreg[1].w
             + zq[8]  * wreg[2].x + zq[9]  * wreg[2].y + zq[10] * wreg[2].z + zq[11] * wreg[2].w
             + zq[12] * wreg[3].x + zq[13] * wreg[3].y + zq[14] * wreg[3].z + zq[15] * wreg[3].w;
    float d1 = zq[0]  * wreg[4].x + zq[1]  * wreg[4].y + zq[2]  * wreg[4].z + zq[3]  * wreg[4].w
             + zq[4]  * wreg[5].x + zq[5]  * wreg[5].y + zq[6]  * wreg[5].z + zq[7]  * wreg[5].w
             + zq[8]  * wreg[6].x + zq[9]  * wreg[6].y + zq[10] * wreg[6].z + zq[11] * wreg[6].w
             + zq[12] * wreg[7].x + zq[13] * wreg[7].y + zq[14] * wreg[7].z + zq[15] * wreg[7].w;

    reinterpret_cast<float2*>(out + row * DOUT)[tid] = make_float2(bp.x + d0, bp.y + d1);
}

extern "C" void kernel_launch(void* const* d_in, const int* in_sizes, int n_in,
                              void* d_out, int out_size)
{
    const float* x         = (const float*)d_in[0];   // [256, 1024]
    const float* W_pre     = (const float*)d_in[1];   // [16, 1024]
    const float* b_pre     = (const float*)d_in[2];   // [16]
    const float* q_weights = (const float*)d_in[3];   // [16]
    const float* W_post    = (const float*)d_in[4];   // [1024, 16]
    const float* b_post    = (const float*)d_in[5];   // [1024]
    float* out             = (float*)d_out;           // [256, 1024]

    quantum_projector_kernel<<<256, 512>>>(x, W_pre, b_pre, q_weights,
                                           W_post, b_post, out);
}